// round 4
// baseline (speedup 1.0000x reference)
#include <cuda_runtime.h>
#include <cstdint>

// Problem constants (fixed by the dataset)
#define NN   2048   // nodes
#define DD   16     // input dim
#define HH   64     // hidden
#define G4   256    // 4*H
#define NCTA 128    // CTAs (1 per SM, all co-resident: 128 <= 148 SMs)
#define ROWS 16     // rows (nodes) per CTA  -> NCTA*ROWS == NN
#define NTH  512    // threads per CTA (16 warps)
#define KT   128    // k-tile for A@q
#define NKT  (NN / KT)   // 16 tiles

typedef unsigned long long u64;

// Global scratch (static __device__ arrays are allowed; no cudaMalloc)
__device__ float g_q[2][NN][HH];           // double-buffered q = tanh(h @ W_q + b_q)
__device__ float g_Apack[(size_t)NN * NN * 2];  // A repacked: [blk][k][r-dup pairs], 32MB
__device__ int   g_bar = 0;                // grid barrier counter (self-resetting)

struct Smem {
  float W_ih[DD][G4];       // 16 KB
  float W_hh[HH][G4];       // 64 KB
  float W_q [HH][HH];       // 16 KB
  float bias[G4];           // 1 KB
  float b_q [HH];
  float W_d [HH];
  float h_loc[ROWS][HH];    // 4 KB  (CTA-private hidden state)
  float c_loc[ROWS][HH];    // 4 KB  (CTA-private cell state)
  float q_tile[KT][HH];     // 32 KB (staged q k-tile; reused as reduction buffer)
  float A_s[KT][2 * ROWS];  // 16 KB (A tile, rows duplicated as {a,a} pairs)
};

__device__ __forceinline__ void fma2(u64& d, u64 a, u64 b) {
  asm("fma.rn.f32x2 %0, %1, %2, %0;" : "+l"(d) : "l"(a), "l"(b));
}
__device__ __forceinline__ u64 pack2(float v) {
  u64 r; asm("mov.b64 %0, {%1, %1};" : "=l"(r) : "f"(v)); return r;
}
__device__ __forceinline__ float2 unpack2(u64 v) {
  float2 r; asm("mov.b64 {%0, %1}, %2;" : "=f"(r.x), "=f"(r.y) : "l"(v)); return r;
}
__device__ __forceinline__ float sigm_f(float x)  { return 1.0f / (1.0f + __expf(-x)); }
__device__ __forceinline__ float tanh_f(float x)  { return 1.0f - 2.0f / (__expf(2.0f * x) + 1.0f); }

__global__ void __launch_bounds__(NTH, 1)
rgcn_kernel(const float* __restrict__ x,    const float* __restrict__ A,
            const float* __restrict__ W_ih, const float* __restrict__ W_hh,
            const float* __restrict__ bias, const float* __restrict__ W_q,
            const float* __restrict__ b_q,  const float* __restrict__ W_d,
            const float* __restrict__ b_d,  float* __restrict__ out, int T)
{
  extern __shared__ unsigned char smem_raw[];
  Smem& s = *reinterpret_cast<Smem*>(smem_raw);

  const int tid  = threadIdx.x;
  const int wid  = tid >> 5;
  const int lane = tid & 31;
  const int n    = blockIdx.x * ROWS + wid;   // this warp's node row (q/gates/act phases)
  const int j0   = 2 * lane;                  // this lane's column pair
  const int rg   = wid & 1;                   // GEMM row group (rows rg*8 .. rg*8+7)
  const int ks   = wid >> 1;                  // GEMM k-slice within tile (16 k each)

  // ---- load constant weights into shared (persist for whole kernel) ----
  for (int i = tid; i < DD * G4; i += NTH) (&s.W_ih[0][0])[i] = W_ih[i];
  for (int i = tid; i < HH * G4; i += NTH) (&s.W_hh[0][0])[i] = W_hh[i];
  for (int i = tid; i < HH * HH; i += NTH) (&s.W_q[0][0])[i]  = W_q[i];
  for (int i = tid; i < G4;      i += NTH) s.bias[i] = bias[i];
  for (int i = tid; i < HH;      i += NTH) { s.b_q[i] = b_q[i]; s.W_d[i] = W_d[i]; }
  for (int i = tid; i < ROWS * HH; i += NTH) {
    (&s.h_loc[0][0])[i] = 0.0f;
    (&s.c_loc[0][0])[i] = 0.0f;
  }

  // ---- one-time repack of this CTA's A rows into {a,a} duplicated pairs ----
  // Layout: g_Apack[blk][k][2*r + {0,1}] = A[blk*16 + r][k]   (blk = blockIdx.x)
  {
    const float* arow = A + (size_t)n * NN;              // warp wid handles row wid
    float* dst = g_Apack + (size_t)blockIdx.x * NN * 2 * ROWS;
    #pragma unroll 1
    for (int c = 0; c < NN / 128; ++c) {                 // 16 chunks of 128 k per warp
      const int k0 = c * 128 + lane * 4;
      const float4 v = __ldg(reinterpret_cast<const float4*>(arow + k0));
      float2 d;
      d.x = v.x; d.y = v.x; *reinterpret_cast<float2*>(dst + (size_t)(k0 + 0) * (2 * ROWS) + 2 * wid) = d;
      d.x = v.y; d.y = v.y; *reinterpret_cast<float2*>(dst + (size_t)(k0 + 1) * (2 * ROWS) + 2 * wid) = d;
      d.x = v.z; d.y = v.z; *reinterpret_cast<float2*>(dst + (size_t)(k0 + 2) * (2 * ROWS) + 2 * wid) = d;
      d.x = v.w; d.y = v.w; *reinterpret_cast<float2*>(dst + (size_t)(k0 + 3) * (2 * ROWS) + 2 * wid) = d;
    }
  }
  __syncthreads();
  const float bd = __ldg(b_d);
  const float* apack_base = g_Apack + (size_t)blockIdx.x * NN * 2 * ROWS;

  for (int t = 0; t < T; ++t) {
    const int p = t & 1;

    // ===== phase 1: q = tanh(h_{t-1} @ W_q + b_q) for own row, write global =====
    {
      float2 acc = make_float2(s.b_q[j0], s.b_q[j0 + 1]);
      #pragma unroll 8
      for (int k = 0; k < HH; ++k) {
        const float hv = s.h_loc[wid][k];              // broadcast LDS
        const float2 wq = *reinterpret_cast<const float2*>(&s.W_q[k][j0]);
        acc.x = fmaf(hv, wq.x, acc.x);
        acc.y = fmaf(hv, wq.y, acc.y);
      }
      float2 qv = make_float2(tanh_f(acc.x), tanh_f(acc.y));
      *reinterpret_cast<float2*>(&g_q[p][n][j0]) = qv;
    }

    // ===== barrier ARRIVE (release q writes) =====
    __threadfence();           // make this thread's q stores visible GPU-wide
    __syncthreads();
    if (tid == 0) atomicAdd(&g_bar, 1);

    // ===== gates = x_t @ W_ih + h @ W_hh + bias  (overlaps other CTAs' q phase) =====
    u64 accg[4];
    #pragma unroll
    for (int m = 0; m < 4; ++m)
      accg[m] = *reinterpret_cast<const u64*>(&s.bias[m * HH + j0]);
    {
      float xreg = (lane < DD) ? __ldg(&x[((size_t)n * T + t) * DD + lane]) : 0.0f;
      #pragma unroll
      for (int d = 0; d < DD; ++d) {
        const u64 xd2 = pack2(__shfl_sync(0xffffffffu, xreg, d));
        #pragma unroll
        for (int m = 0; m < 4; ++m)
          fma2(accg[m], xd2, *reinterpret_cast<const u64*>(&s.W_ih[d][m * HH + j0]));
      }
      #pragma unroll 4
      for (int k = 0; k < HH; ++k) {
        const u64 h2 = pack2(s.h_loc[wid][k]);      // broadcast LDS
        #pragma unroll
        for (int m = 0; m < 4; ++m)
          fma2(accg[m], h2, *reinterpret_cast<const u64*>(&s.W_hh[k][m * HH + j0]));
      }
    }

    // ===== barrier WAIT (acquire others' q) =====
    if (tid == 0) {
      const int target = NCTA * (t + 1);
      while (*((volatile int*)&g_bar) < target) { }
    }
    __syncthreads();

    // ===== phase 2: Aq = A @ q, register-blocked (8 rows/warp, 8-way k-split) =====
    u64 acc[8];
    #pragma unroll
    for (int r = 0; r < 8; ++r) acc[r] = 0ull;

    #pragma unroll 1
    for (int kt = 0; kt < NKT; ++kt) {
      // stage q tile (L2-only loads: q was written by other SMs)
      {
        const float4* src = reinterpret_cast<const float4*>(&g_q[p][kt * KT][0]);
        float4* dst = reinterpret_cast<float4*>(&s.q_tile[0][0]);
        #pragma unroll
        for (int i = 0; i < (KT * HH / 4) / NTH; ++i)
          dst[tid + i * NTH] = __ldcg(src + tid + i * NTH);
      }
      // stage A dup tile (contiguous copy from precomputed pack; A is L2-resident)
      {
        const float4* src = reinterpret_cast<const float4*>(apack_base + (size_t)kt * KT * (2 * ROWS));
        float4* dst = reinterpret_cast<float4*>(&s.A_s[0][0]);
        #pragma unroll
        for (int i = 0; i < (KT * 2 * ROWS / 4) / NTH; ++i)
          dst[tid + i * NTH] = src[tid + i * NTH];
      }
      __syncthreads();

      const int kbase = ks * 16;
      #pragma unroll 4
      for (int kk = 0; kk < 16; ++kk) {
        const int k = kbase + kk;
        // two LDS.128 broadcasts give four {a,a} pairs each for this row group
        const ulonglong2 d01 = *reinterpret_cast<const ulonglong2*>(&s.A_s[k][rg * 16 + 0]);
        const ulonglong2 d23 = *reinterpret_cast<const ulonglong2*>(&s.A_s[k][rg * 16 + 4]);
        const ulonglong2 d45 = *reinterpret_cast<const ulonglong2*>(&s.A_s[k][rg * 16 + 8]);
        const ulonglong2 d67 = *reinterpret_cast<const ulonglong2*>(&s.A_s[k][rg * 16 + 12]);
        const u64 q2 = *reinterpret_cast<const u64*>(&s.q_tile[k][j0]);
        fma2(acc[0], d01.x, q2);
        fma2(acc[1], d01.y, q2);
        fma2(acc[2], d23.x, q2);
        fma2(acc[3], d23.y, q2);
        fma2(acc[4], d45.x, q2);
        fma2(acc[5], d45.y, q2);
        fma2(acc[6], d67.x, q2);
        fma2(acc[7], d67.y, q2);
      }
      __syncthreads();
    }

    // ===== reduce the 8 k-slice partials (reuse q_tile as [8][16][64] buffer) =====
    float* red = &s.q_tile[0][0];
    #pragma unroll
    for (int r = 0; r < 8; ++r)
      *reinterpret_cast<u64*>(&red[((ks << 4) + (rg << 3) + r) * HH + j0]) = acc[r];
    __syncthreads();
    float2 aqv = make_float2(0.0f, 0.0f);
    #pragma unroll
    for (int sl = 0; sl < 8; ++sl) {
      const float2 v = *reinterpret_cast<const float2*>(&red[((sl << 4) + wid) * HH + j0]);
      aqv.x += v.x; aqv.y += v.y;
    }

    // ===== activations + state update (warp wid owns row wid) =====
    {
      const float2 gi = unpack2(accg[0]);
      const float2 gf = unpack2(accg[1]);
      const float2 gg = unpack2(accg[2]);
      const float2 go = unpack2(accg[3]);
      const float2 cold = *reinterpret_cast<const float2*>(&s.c_loc[wid][j0]);

      const float i0 = sigm_f(gi.x), i1 = sigm_f(gi.y);
      const float f0 = sigm_f(gf.x), f1 = sigm_f(gf.y);
      const float gg0 = tanh_f(gg.x), gg1 = tanh_f(gg.y);
      const float o0 = sigm_f(go.x), o1 = sigm_f(go.y);

      const float c0 = f0 * (cold.x + aqv.x) + i0 * gg0;
      const float c1 = f1 * (cold.y + aqv.y) + i1 * gg1;
      const float h0 = o0 * tanh_f(c0);
      const float h1 = o1 * tanh_f(c1);

      *reinterpret_cast<float2*>(&s.c_loc[wid][j0]) = make_float2(c0, c1);
      *reinterpret_cast<float2*>(&s.h_loc[wid][j0]) = make_float2(h0, h1);

      // out[n, t] = h_t @ W_dense + b_dense   (warp reduction)
      float part = h0 * s.W_d[j0] + h1 * s.W_d[j0 + 1];
      #pragma unroll
      for (int off = 16; off > 0; off >>= 1)
        part += __shfl_down_sync(0xffffffffu, part, off);
      if (lane == 0) out[(size_t)n * T + t] = part + bd;
    }
    __syncthreads();   // red buffer reads done; h/c updated before next step's phases
  }

  // ===== self-resetting barrier counter: last CTA to finish zeroes it =====
  if (tid == 0) {
    const int ticket = atomicAdd(&g_bar, 1);
    if (ticket == NCTA * (T + 1) - 1) {
      atomicExch(&g_bar, 0);     // persists to next launch / graph replay
    }
  }
}

extern "C" void kernel_launch(void* const* d_in, const int* in_sizes, int n_in,
                              void* d_out, int out_size) {
  const float* x    = (const float*)d_in[0];
  const float* A    = (const float*)d_in[1];
  const float* W_ih = (const float*)d_in[2];
  const float* W_hh = (const float*)d_in[3];
  const float* bias = (const float*)d_in[4];
  const float* W_q  = (const float*)d_in[5];
  const float* b_q  = (const float*)d_in[6];
  const float* W_d  = (const float*)d_in[7];
  const float* b_d  = (const float*)d_in[8];
  float* out = (float*)d_out;

  const int T = in_sizes[0] / (NN * DD);   // 365

  cudaFuncSetAttribute(rgcn_kernel,
                       cudaFuncAttributeMaxDynamicSharedMemorySize,
                       (int)sizeof(Smem));
  rgcn_kernel<<<NCTA, NTH, sizeof(Smem)>>>(x, A, W_ih, W_hh, bias,
                                           W_q, b_q, W_d, b_d, out, T);
}

// round 8
// speedup vs baseline: 2.2015x; 2.2015x over previous
#include <cuda_runtime.h>
#include <cstdint>

#define NN   2048
#define DD   16
#define HH   64
#define G4   256
#define NCTA 128
#define ROWS 16
#define NTH  512
#define KT   128          // k per staged q tile
#define NKT  (NN / KT)    // 16 tiles
#define QPAD 72           // padded q_tile row (bank-conflict-free B frags)

typedef unsigned long long u64;
typedef unsigned int u32;

// Global scratch (no cudaMalloc)
__device__ u32 g_q[2][NN][HH];                  // q (tf32 bit patterns), double buffered
__device__ u32 g_Afrag[(size_t)NCTA * 8192 * 4]; // A in mma-fragment order, 16MB
__device__ int g_bar = 0;                        // grid barrier (self-resetting)

struct Smem {
  float qt[2][KT][QPAD];    // 73.7 KB; also aliased as red[16][16][64] (64KB)
  float W_ih[DD][G4];       // 16 KB
  float W_hh[HH][G4];       // 64 KB
  float W_q [HH][HH];       // 16 KB
  float bias[G4];
  float b_q [HH];
  float W_d [HH];
  float h_loc[ROWS][HH];
  float c_loc[ROWS][HH];
};

__device__ __forceinline__ u32 smem_u32(const void* p) { return (u32)__cvta_generic_to_shared(p); }
__device__ __forceinline__ void cp16(u32 dst, const void* src) {
  asm volatile("cp.async.cg.shared.global [%0], [%1], 16;"
               :: "r"(dst), "l"(__cvta_generic_to_global(src)) : "memory");
}
__device__ __forceinline__ u32 cvt_tf32(float v) {
  u32 r; asm("cvt.rna.tf32.f32 %0, %1;" : "=r"(r) : "f"(v)); return r;
}
__device__ __forceinline__ void mma8(float* c, uint4 a, u32 b0, u32 b1) {
  asm volatile("mma.sync.aligned.m16n8k8.row.col.f32.tf32.tf32.f32 "
               "{%0,%1,%2,%3}, {%4,%5,%6,%7}, {%8,%9}, {%0,%1,%2,%3};"
               : "+f"(c[0]), "+f"(c[1]), "+f"(c[2]), "+f"(c[3])
               : "r"(a.x), "r"(a.y), "r"(a.z), "r"(a.w), "r"(b0), "r"(b1));
}
__device__ __forceinline__ void fma2(u64& d, u64 a, u64 b) {
  asm("fma.rn.f32x2 %0, %1, %2, %0;" : "+l"(d) : "l"(a), "l"(b));
}
__device__ __forceinline__ u64 pack2(float v) {
  u64 r; asm("mov.b64 %0, {%1, %1};" : "=l"(r) : "f"(v)); return r;
}
__device__ __forceinline__ float2 unpack2(u64 v) {
  float2 r; asm("mov.b64 {%0, %1}, %2;" : "=f"(r.x), "=f"(r.y) : "l"(v)); return r;
}
__device__ __forceinline__ float sigm_f(float x) { return 1.0f / (1.0f + __expf(-x)); }
__device__ __forceinline__ float tanh_f(float x) { return 1.0f - 2.0f / (__expf(2.0f * x) + 1.0f); }

// Stage q tile kt (128 rows x 64 cols) into qt[buf] via cp.async.cg (L2-only reads)
__device__ __forceinline__ void stage_q(Smem& s, int buf, int kt, const u32* qb, int tid) {
  #pragma unroll
  for (int i = 0; i < 4; ++i) {
    const int idx = tid + i * NTH;        // 2048 x 16B ops
    const int row = idx >> 4;
    const int c4  = (idx & 15) << 2;
    cp16(smem_u32(&s.qt[buf][row][c4]), qb + (size_t)(kt * KT + row) * HH + c4);
  }
}

__global__ void __launch_bounds__(NTH, 1)
rgcn_kernel(const float* __restrict__ x,    const float* __restrict__ A,
            const float* __restrict__ W_ih, const float* __restrict__ W_hh,
            const float* __restrict__ bias, const float* __restrict__ W_q,
            const float* __restrict__ b_q,  const float* __restrict__ W_d,
            const float* __restrict__ b_d,  float* __restrict__ out, int T)
{
  extern __shared__ unsigned char smem_raw[];
  Smem& s = *reinterpret_cast<Smem*>(smem_raw);

  const int tid = threadIdx.x, wid = tid >> 5, lane = tid & 31;
  const int n_base = blockIdx.x * ROWS;
  const int n  = n_base + wid;              // this warp's node row (q/gates/act)
  const int j0 = 2 * lane;

  // ---- weights/state into shared ----
  for (int i = tid; i < DD * G4; i += NTH) (&s.W_ih[0][0])[i] = W_ih[i];
  for (int i = tid; i < HH * G4; i += NTH) (&s.W_hh[0][0])[i] = W_hh[i];
  for (int i = tid; i < HH * HH; i += NTH) (&s.W_q[0][0])[i]  = W_q[i];
  for (int i = tid; i < G4;      i += NTH) s.bias[i] = bias[i];
  for (int i = tid; i < HH;      i += NTH) { s.b_q[i] = b_q[i]; s.W_d[i] = W_d[i]; }
  for (int i = tid; i < ROWS * HH; i += NTH) {
    (&s.h_loc[0][0])[i] = 0.0f; (&s.c_loc[0][0])[i] = 0.0f;
  }

  // ---- one-time: pack this CTA's A rows into mma-fragment order (tf32) ----
  // frag f = kt*16 + w covers k0 = kt*128 + w*8; lane l holds
  // {A[g][k0+tg], A[g+8][k0+tg], A[g][k0+tg+4], A[g+8][k0+tg+4]}, g=l>>2, tg=l&3
  for (int i = tid; i < 8192; i += NTH) {
    const int frag = i >> 5, ln = i & 31;
    const int kt = frag >> 4, w = frag & 15;
    const int k0 = kt * KT + (w << 3);
    const int g = ln >> 2, tg = ln & 3;
    const float* r0 = A + (size_t)(n_base + g) * NN;
    const float* r8 = A + (size_t)(n_base + g + 8) * NN;
    uint4 v;
    v.x = cvt_tf32(__ldg(r0 + k0 + tg));
    v.y = cvt_tf32(__ldg(r8 + k0 + tg));
    v.z = cvt_tf32(__ldg(r0 + k0 + tg + 4));
    v.w = cvt_tf32(__ldg(r8 + k0 + tg + 4));
    *reinterpret_cast<uint4*>(&g_Afrag[((size_t)blockIdx.x * 8192 + i) * 4]) = v;
  }
  __syncthreads();
  const float bd = __ldg(b_d);
  const u32* fragbase = g_Afrag + (size_t)blockIdx.x * 8192 * 4 + (size_t)wid * 32 * 4 + (size_t)lane * 4;

  for (int t = 0; t < T; ++t) {
    const int p = t & 1;
    const u32* qb = &g_q[p][0][0];

    // ===== phase 1: q = tanh(h @ W_q + b_q), tf32-rounded, [n][j] layout =====
    {
      float2 acc = make_float2(s.b_q[j0], s.b_q[j0 + 1]);
      #pragma unroll 8
      for (int k = 0; k < HH; ++k) {
        const float hv = s.h_loc[wid][k];
        const float2 wq = *reinterpret_cast<const float2*>(&s.W_q[k][j0]);
        acc.x = fmaf(hv, wq.x, acc.x); acc.y = fmaf(hv, wq.y, acc.y);
      }
      const u32 qlo = cvt_tf32(tanh_f(acc.x));
      const u32 qhi = cvt_tf32(tanh_f(acc.y));
      *reinterpret_cast<u64*>(&g_q[p][n][j0]) = (u64)qlo | ((u64)qhi << 32);
    }

    // ===== barrier ARRIVE (release q writes) =====
    __threadfence();
    __syncthreads();
    if (tid == 0) atomicAdd(&g_bar, 1);

    // ===== gates = x_t @ W_ih + h @ W_hh + bias (overlaps other CTAs' q) =====
    u64 accg[4];
    #pragma unroll
    for (int m = 0; m < 4; ++m) accg[m] = *reinterpret_cast<const u64*>(&s.bias[m * HH + j0]);
    {
      float xreg = (lane < DD) ? __ldg(&x[((size_t)n * T + t) * DD + lane]) : 0.0f;
      #pragma unroll
      for (int d = 0; d < DD; ++d) {
        const u64 xd2 = pack2(__shfl_sync(0xffffffffu, xreg, d));
        #pragma unroll
        for (int m = 0; m < 4; ++m)
          fma2(accg[m], xd2, *reinterpret_cast<const u64*>(&s.W_ih[d][m * HH + j0]));
      }
      #pragma unroll 4
      for (int k = 0; k < HH; ++k) {
        const u64 h2 = pack2(s.h_loc[wid][k]);
        #pragma unroll
        for (int m = 0; m < 4; ++m)
          fma2(accg[m], h2, *reinterpret_cast<const u64*>(&s.W_hh[k][m * HH + j0]));
      }
    }

    // ===== barrier WAIT (acquire all q; cp.async.cg reads L2 directly) =====
    if (tid == 0) {
      const int target = NCTA * (t + 1);
      while (*((volatile int*)&g_bar) < target) { }
    }
    __syncthreads();

    // ===== phase 2: D[16x64] = A_rows @ q via mma.sync tf32, k-split 16 warps =====
    float acc[32];
    #pragma unroll
    for (int i = 0; i < 32; ++i) acc[i] = 0.0f;

    stage_q(s, 0, 0, qb, tid);
    asm volatile("cp.async.commit_group;" ::: "memory");
    uint4 frag = *reinterpret_cast<const uint4*>(fragbase);   // tile 0 A-frag

    const int row0 = (wid << 3) + (lane & 3);   // this warp's k-sub rows in tile
    const int bcol = lane >> 2;

    #pragma unroll 1
    for (int c = 0; c < NKT; ++c) {
      if (c + 1 < NKT) {
        stage_q(s, (c + 1) & 1, c + 1, qb, tid);
        asm volatile("cp.async.commit_group;" ::: "memory");
        asm volatile("cp.async.wait_group 1;" ::: "memory");
      } else {
        asm volatile("cp.async.wait_group 0;" ::: "memory");
      }
      __syncthreads();

      uint4 nfrag;
      if (c + 1 < NKT)
        nfrag = *reinterpret_cast<const uint4*>(fragbase + ((size_t)(c + 1) * 16 * 32) * 4);

      const float* qtile = &s.qt[c & 1][0][0];
      const float* brow0 = qtile + row0 * QPAD + bcol;
      #pragma unroll
      for (int nc = 0; nc < 8; ++nc) {
        const u32 b0 = __float_as_uint(brow0[nc * 8]);
        const u32 b1 = __float_as_uint(brow0[4 * QPAD + nc * 8]);
        mma8(acc + nc * 4, frag, b0, b1);
      }
      frag = nfrag;
      __syncthreads();   // all warps done with qt[c&1] before restage at c+1
    }

    // ===== reduce k-split partials via smem (alias qt as red[16][16][64]) =====
    float* red = &s.qt[0][0][0];
    {
      const int r = lane >> 2, cc = (lane & 3) * 2;
      #pragma unroll
      for (int nc = 0; nc < 8; ++nc) {
        *reinterpret_cast<float2*>(&red[wid * 1024 + r * 64 + nc * 8 + cc]) =
            make_float2(acc[nc * 4 + 0], acc[nc * 4 + 1]);
        *reinterpret_cast<float2*>(&red[wid * 1024 + (r + 8) * 64 + nc * 8 + cc]) =
            make_float2(acc[nc * 4 + 2], acc[nc * 4 + 3]);
      }
    }
    __syncthreads();
    float2 aqv = make_float2(0.0f, 0.0f);
    #pragma unroll
    for (int w2 = 0; w2 < 16; ++w2) {
      const float2 v = *reinterpret_cast<const float2*>(&red[w2 * 1024 + wid * 64 + j0]);
      aqv.x += v.x; aqv.y += v.y;
    }

    // ===== activations + state update (warp wid owns row wid) =====
    {
      const float2 gi = unpack2(accg[0]), gf = unpack2(accg[1]);
      const float2 gg = unpack2(accg[2]), go = unpack2(accg[3]);
      const float2 cold = *reinterpret_cast<const float2*>(&s.c_loc[wid][j0]);

      const float i0 = sigm_f(gi.x), i1 = sigm_f(gi.y);
      const float f0 = sigm_f(gf.x), f1 = sigm_f(gf.y);
      const float g0 = tanh_f(gg.x), g1 = tanh_f(gg.y);
      const float o0 = sigm_f(go.x), o1 = sigm_f(go.y);

      const float c0 = f0 * (cold.x + aqv.x) + i0 * g0;
      const float c1 = f1 * (cold.y + aqv.y) + i1 * g1;
      const float h0 = o0 * tanh_f(c0);
      const float h1 = o1 * tanh_f(c1);

      *reinterpret_cast<float2*>(&s.c_loc[wid][j0]) = make_float2(c0, c1);
      *reinterpret_cast<float2*>(&s.h_loc[wid][j0]) = make_float2(h0, h1);

      float part = h0 * s.W_d[j0] + h1 * s.W_d[j0 + 1];
      #pragma unroll
      for (int off = 16; off > 0; off >>= 1)
        part += __shfl_down_sync(0xffffffffu, part, off);
      if (lane == 0) out[(size_t)n * T + t] = part + bd;
    }
    __syncthreads();   // red reads done before next step's staging reuses qt
  }

  // ===== self-resetting barrier counter =====
  if (tid == 0) {
    const int ticket = atomicAdd(&g_bar, 1);
    if (ticket == NCTA * (T + 1) - 1) atomicExch(&g_bar, 0);
  }
}

extern "C" void kernel_launch(void* const* d_in, const int* in_sizes, int n_in,
                              void* d_out, int out_size) {
  const float* x    = (const float*)d_in[0];
  const float* A    = (const float*)d_in[1];
  const float* W_ih = (const float*)d_in[2];
  const float* W_hh = (const float*)d_in[3];
  const float* bias = (const float*)d_in[4];
  const float* W_q  = (const float*)d_in[5];
  const float* b_q  = (const float*)d_in[6];
  const float* W_d  = (const float*)d_in[7];
  const float* b_d  = (const float*)d_in[8];
  float* out = (float*)d_out;

  const int T = in_sizes[0] / (NN * DD);   // 365

  cudaFuncSetAttribute(rgcn_kernel, cudaFuncAttributeMaxDynamicSharedMemorySize,
                       (int)sizeof(Smem));
  rgcn_kernel<<<NCTA, NTH, sizeof(Smem)>>>(x, A, W_ih, W_hh, bias,
                                           W_q, b_q, W_d, b_d, out, T);
}

// round 9
// speedup vs baseline: 2.4064x; 1.0931x over previous
#include <cuda_runtime.h>
#include <cstdint>

#define NN   2048
#define DD   16
#define HH   64
#define G4   256
#define NCTA 128
#define ROWS 16
#define NTH  512
#define KT   128          // k per staged q tile
#define NKT  (NN / KT)    // 16 tiles
#define QPAD 72           // padded q_tile row (bank-conflict-free B frags)

typedef unsigned long long u64;
typedef unsigned int u32;

// Global scratch (no cudaMalloc)
__device__ u32 g_q[2][NN][HH];                   // q (tf32 bit patterns), double buffered
__device__ u32 g_Afrag[(size_t)NCTA * 8192 * 4]; // A in mma-fragment order, 16MB
__device__ int g_bar = 0;                        // grid barrier (self-resetting)

struct Smem {
  // qt: staging buffers for A@q; also aliased (time-multiplexed) as:
  //   qred[4][16][64] (16KB, q-phase k-split reduce)
  //   red [16][16][64] (64KB, A@q k-split reduce)
  //   gate_s[16][256]  (16KB, gate redistribution, after red consumed)
  float qt[2][KT][QPAD];    // 73.7 KB
  float W_ih[DD][G4];       // 16 KB
  float W_hh[HH][G4];       // 64 KB
  float W_q [HH][HH];       // 16 KB
  float bias[G4];
  float b_q [HH];
  float W_d [HH];
  float hdup[HH][18][2];    // h duplicated {h,h}, transposed: [k][row][2] (9.2KB)
  float xdup[DD][18][2];    // x_t duplicated, transposed: [d][row][2]
};

__device__ __forceinline__ u32 smem_u32(const void* p) { return (u32)__cvta_generic_to_shared(p); }
__device__ __forceinline__ void cp16(u32 dst, const void* src) {
  asm volatile("cp.async.cg.shared.global [%0], [%1], 16;"
               :: "r"(dst), "l"(__cvta_generic_to_global(src)) : "memory");
}
__device__ __forceinline__ u32 cvt_tf32(float v) {
  u32 r; asm("cvt.rna.tf32.f32 %0, %1;" : "=r"(r) : "f"(v)); return r;
}
__device__ __forceinline__ void mma8(float* c, uint4 a, u32 b0, u32 b1) {
  asm volatile("mma.sync.aligned.m16n8k8.row.col.f32.tf32.tf32.f32 "
               "{%0,%1,%2,%3}, {%4,%5,%6,%7}, {%8,%9}, {%0,%1,%2,%3};"
               : "+f"(c[0]), "+f"(c[1]), "+f"(c[2]), "+f"(c[3])
               : "r"(a.x), "r"(a.y), "r"(a.z), "r"(a.w), "r"(b0), "r"(b1));
}
__device__ __forceinline__ void fma2(u64& d, u64 a, u64 b) {
  asm("fma.rn.f32x2 %0, %1, %2, %0;" : "+l"(d) : "l"(a), "l"(b));
}
__device__ __forceinline__ u64 pack2(float v) {
  u64 r; asm("mov.b64 %0, {%1, %1};" : "=l"(r) : "f"(v)); return r;
}
__device__ __forceinline__ float2 unpack2(u64 v) {
  float2 r; asm("mov.b64 {%0, %1}, %2;" : "=f"(r.x), "=f"(r.y) : "l"(v)); return r;
}
__device__ __forceinline__ float sigm_f(float x) { return 1.0f / (1.0f + __expf(-x)); }
__device__ __forceinline__ float tanh_f(float x) { return 1.0f - 2.0f / (__expf(2.0f * x) + 1.0f); }

// Stage q tile kt (128 rows x 64 cols) into qt[buf] via cp.async.cg (L2-only reads)
__device__ __forceinline__ void stage_q(Smem& s, int buf, int kt, const u32* qb, int tid) {
  #pragma unroll
  for (int i = 0; i < 4; ++i) {
    const int idx = tid + i * NTH;        // 2048 x 16B ops
    const int row = idx >> 4;
    const int c4  = (idx & 15) << 2;
    cp16(smem_u32(&s.qt[buf][row][c4]), qb + (size_t)(kt * KT + row) * HH + c4);
  }
}

__global__ void __launch_bounds__(NTH, 1)
rgcn_kernel(const float* __restrict__ x,    const float* __restrict__ A,
            const float* __restrict__ W_ih, const float* __restrict__ W_hh,
            const float* __restrict__ bias, const float* __restrict__ W_q,
            const float* __restrict__ b_q,  const float* __restrict__ W_d,
            const float* __restrict__ b_d,  float* __restrict__ out, int T)
{
  extern __shared__ unsigned char smem_raw[];
  Smem& s = *reinterpret_cast<Smem*>(smem_raw);

  const int tid = threadIdx.x, wid = tid >> 5, lane = tid & 31;
  const int n_base = blockIdx.x * ROWS;
  const int n   = n_base + wid;             // this warp's node row (q-reduce/act/out)
  const int j0  = 2 * lane;                 // col pair within a 64-block
  const int rw4 = (wid >> 2) * 4;           // gates/q: 4-row group base
  const int cw  = wid & 3;                  // gates: 64-col block  |  q: k-slice
  const int gc0 = cw * 64 + j0;             // gates: absolute col pair base

  // ---- weights into shared ----
  for (int i = tid; i < DD * G4; i += NTH) (&s.W_ih[0][0])[i] = W_ih[i];
  for (int i = tid; i < HH * G4; i += NTH) (&s.W_hh[0][0])[i] = W_hh[i];
  for (int i = tid; i < HH * HH; i += NTH) (&s.W_q[0][0])[i]  = W_q[i];
  for (int i = tid; i < G4;      i += NTH) s.bias[i] = bias[i];
  for (int i = tid; i < HH;      i += NTH) { s.b_q[i] = b_q[i]; s.W_d[i] = W_d[i]; }
  for (int i = tid; i < HH * 18 * 2; i += NTH) (&s.hdup[0][0][0])[i] = 0.0f;

  // ---- one-time: pack this CTA's A rows into mma-fragment order (tf32) ----
  for (int i = tid; i < 8192; i += NTH) {
    const int frag = i >> 5, ln = i & 31;
    const int kt = frag >> 4, w = frag & 15;
    const int k0 = kt * KT + (w << 3);
    const int g = ln >> 2, tg = ln & 3;
    const float* r0 = A + (size_t)(n_base + g) * NN;
    const float* r8 = A + (size_t)(n_base + g + 8) * NN;
    uint4 v;
    v.x = cvt_tf32(__ldg(r0 + k0 + tg));
    v.y = cvt_tf32(__ldg(r8 + k0 + tg));
    v.z = cvt_tf32(__ldg(r0 + k0 + tg + 4));
    v.w = cvt_tf32(__ldg(r8 + k0 + tg + 4));
    *reinterpret_cast<uint4*>(&g_Afrag[((size_t)blockIdx.x * 8192 + i) * 4]) = v;
  }
  __syncthreads();
  const float bd = __ldg(b_d);
  const u32* fragbase = g_Afrag + (size_t)blockIdx.x * 8192 * 4 + (size_t)wid * 32 * 4 + (size_t)lane * 4;

  float c0r = 0.0f, c1r = 0.0f;    // cell state lives in registers (fixed ownership)

  for (int t = 0; t < T; ++t) {
    const int p = t & 1;
    const u32* qb = &g_q[p][0][0];

    // ===== stage x_t into duplicated-transposed smem =====
    if (tid < 256) {
      const int r = tid >> 4, d = tid & 15;
      const float xv = __ldg(&x[((size_t)(n_base + r) * T + t) * DD + d]);
      *reinterpret_cast<u64*>(&s.xdup[d][r][0]) = pack2(xv);
    }

    // ===== phase 1: q = tanh(h @ W_q + b_q); warp=(4 rows, k-slice cw*16) =====
    {
      u64 qacc[4] = {0ull, 0ull, 0ull, 0ull};
      #pragma unroll
      for (int kk = 0; kk < 16; ++kk) {
        const int k = (cw << 4) + kk;
        const u64 w2 = *reinterpret_cast<const u64*>(&s.W_q[k][j0]);
        const ulonglong2 h01 = *reinterpret_cast<const ulonglong2*>(&s.hdup[k][rw4][0]);
        const ulonglong2 h23 = *reinterpret_cast<const ulonglong2*>(&s.hdup[k][rw4 + 2][0]);
        fma2(qacc[0], h01.x, w2); fma2(qacc[1], h01.y, w2);
        fma2(qacc[2], h23.x, w2); fma2(qacc[3], h23.y, w2);
      }
      float* qred = &s.qt[0][0][0];          // [4][16][64]
      #pragma unroll
      for (int rr = 0; rr < 4; ++rr)
        *reinterpret_cast<u64*>(&qred[(cw << 10) + (rw4 + rr) * 64 + j0]) = qacc[rr];
    }
    __syncthreads();
    {
      const float* qred = &s.qt[0][0][0];
      float2 qs = make_float2(s.b_q[j0], s.b_q[j0 + 1]);
      #pragma unroll
      for (int kq = 0; kq < 4; ++kq) {
        const float2 v = *reinterpret_cast<const float2*>(&qred[(kq << 10) + wid * 64 + j0]);
        qs.x += v.x; qs.y += v.y;
      }
      const u32 qlo = cvt_tf32(tanh_f(qs.x));
      const u32 qhi = cvt_tf32(tanh_f(qs.y));
      *reinterpret_cast<u64*>(&g_q[p][n][j0]) = (u64)qlo | ((u64)qhi << 32);
    }

    // ===== barrier ARRIVE (release q writes) =====
    __threadfence();
    __syncthreads();
    if (tid == 0) atomicAdd(&g_bar, 1);

    // ===== gates: warp=(4 rows rw4.., 64-col block cw); overlaps barrier skew =====
    u64 accg[4];
    {
      const u64 b2 = *reinterpret_cast<const u64*>(&s.bias[gc0]);
      accg[0] = b2; accg[1] = b2; accg[2] = b2; accg[3] = b2;
      #pragma unroll
      for (int d = 0; d < DD; ++d) {
        const u64 w2 = *reinterpret_cast<const u64*>(&s.W_ih[d][gc0]);
        const ulonglong2 x01 = *reinterpret_cast<const ulonglong2*>(&s.xdup[d][rw4][0]);
        const ulonglong2 x23 = *reinterpret_cast<const ulonglong2*>(&s.xdup[d][rw4 + 2][0]);
        fma2(accg[0], x01.x, w2); fma2(accg[1], x01.y, w2);
        fma2(accg[2], x23.x, w2); fma2(accg[3], x23.y, w2);
      }
      #pragma unroll 8
      for (int k = 0; k < HH; ++k) {
        const u64 w2 = *reinterpret_cast<const u64*>(&s.W_hh[k][gc0]);
        const ulonglong2 h01 = *reinterpret_cast<const ulonglong2*>(&s.hdup[k][rw4][0]);
        const ulonglong2 h23 = *reinterpret_cast<const ulonglong2*>(&s.hdup[k][rw4 + 2][0]);
        fma2(accg[0], h01.x, w2); fma2(accg[1], h01.y, w2);
        fma2(accg[2], h23.x, w2); fma2(accg[3], h23.y, w2);
      }
    }

    // ===== barrier WAIT (acquire all q; cp.async.cg reads L2 directly) =====
    if (tid == 0) {
      const int target = NCTA * (t + 1);
      while (*((volatile int*)&g_bar) < target) { }
    }
    __syncthreads();

    // ===== phase 2: D[16x64] = A_rows @ q via mma.sync tf32, k-split 16 warps =====
    float acc[32];
    #pragma unroll
    for (int i = 0; i < 32; ++i) acc[i] = 0.0f;

    stage_q(s, 0, 0, qb, tid);
    asm volatile("cp.async.commit_group;" ::: "memory");
    uint4 frag = *reinterpret_cast<const uint4*>(fragbase);

    const int row0 = (wid << 3) + (lane & 3);
    const int bcol = lane >> 2;

    #pragma unroll 1
    for (int c = 0; c < NKT; ++c) {
      if (c + 1 < NKT) {
        stage_q(s, (c + 1) & 1, c + 1, qb, tid);
        asm volatile("cp.async.commit_group;" ::: "memory");
        asm volatile("cp.async.wait_group 1;" ::: "memory");
      } else {
        asm volatile("cp.async.wait_group 0;" ::: "memory");
      }
      __syncthreads();

      uint4 nfrag;
      if (c + 1 < NKT)
        nfrag = *reinterpret_cast<const uint4*>(fragbase + ((size_t)(c + 1) * 16 * 32) * 4);

      const float* qtile = &s.qt[c & 1][0][0];
      const float* brow0 = qtile + row0 * QPAD + bcol;
      #pragma unroll
      for (int nc = 0; nc < 8; ++nc) {
        const u32 b0 = __float_as_uint(brow0[nc * 8]);
        const u32 b1 = __float_as_uint(brow0[4 * QPAD + nc * 8]);
        mma8(acc + nc * 4, frag, b0, b1);
      }
      frag = nfrag;
      __syncthreads();
    }

    // ===== reduce A@q k-split partials (red[16][16][64] aliases qt) =====
    float* red = &s.qt[0][0][0];
    {
      const int r = lane >> 2, cc = (lane & 3) * 2;
      #pragma unroll
      for (int nc = 0; nc < 8; ++nc) {
        *reinterpret_cast<float2*>(&red[wid * 1024 + r * 64 + nc * 8 + cc]) =
            make_float2(acc[nc * 4 + 0], acc[nc * 4 + 1]);
        *reinterpret_cast<float2*>(&red[wid * 1024 + (r + 8) * 64 + nc * 8 + cc]) =
            make_float2(acc[nc * 4 + 2], acc[nc * 4 + 3]);
      }
    }
    __syncthreads();
    float2 aqv = make_float2(0.0f, 0.0f);
    #pragma unroll
    for (int w2 = 0; w2 < 16; ++w2) {
      const float2 v = *reinterpret_cast<const float2*>(&red[w2 * 1024 + wid * 64 + j0]);
      aqv.x += v.x; aqv.y += v.y;
    }
    __syncthreads();                      // red fully consumed before gate_s overwrite

    // ===== redistribute gates: (4-row x 64-col blocks) -> row-major gate_s =====
    float* gs = &s.qt[0][0][0];           // gate_s[16][256]
    #pragma unroll
    for (int rr = 0; rr < 4; ++rr)
      *reinterpret_cast<u64*>(&gs[(rw4 + rr) * 256 + gc0]) = accg[rr];
    __syncthreads();

    // ===== activations + state update (warp wid owns row wid; c in registers) =====
    {
      const float2 gi = *reinterpret_cast<const float2*>(&gs[wid * 256 +   0 + j0]);
      const float2 gf = *reinterpret_cast<const float2*>(&gs[wid * 256 +  64 + j0]);
      const float2 gg = *reinterpret_cast<const float2*>(&gs[wid * 256 + 128 + j0]);
      const float2 go = *reinterpret_cast<const float2*>(&gs[wid * 256 + 192 + j0]);

      const float i0 = sigm_f(gi.x), i1 = sigm_f(gi.y);
      const float f0 = sigm_f(gf.x), f1 = sigm_f(gf.y);
      const float g0 = tanh_f(gg.x), g1 = tanh_f(gg.y);
      const float o0 = sigm_f(go.x), o1 = sigm_f(go.y);

      c0r = f0 * (c0r + aqv.x) + i0 * g0;
      c1r = f1 * (c1r + aqv.y) + i1 * g1;
      const float h0 = o0 * tanh_f(c0r);
      const float h1 = o1 * tanh_f(c1r);

      *reinterpret_cast<u64*>(&s.hdup[j0    ][wid][0]) = pack2(h0);
      *reinterpret_cast<u64*>(&s.hdup[j0 + 1][wid][0]) = pack2(h1);

      float part = h0 * s.W_d[j0] + h1 * s.W_d[j0 + 1];
      #pragma unroll
      for (int off = 16; off > 0; off >>= 1)
        part += __shfl_down_sync(0xffffffffu, part, off);
      if (lane == 0) out[(size_t)n * T + t] = part + bd;
    }
    __syncthreads();                      // gs consumed + hdup ready for next step
  }

  // ===== self-resetting barrier counter =====
  if (tid == 0) {
    const int ticket = atomicAdd(&g_bar, 1);
    if (ticket == NCTA * (T + 1) - 1) atomicExch(&g_bar, 0);
  }
}

extern "C" void kernel_launch(void* const* d_in, const int* in_sizes, int n_in,
                              void* d_out, int out_size) {
  const float* x    = (const float*)d_in[0];
  const float* A    = (const float*)d_in[1];
  const float* W_ih = (const float*)d_in[2];
  const float* W_hh = (const float*)d_in[3];
  const float* bias = (const float*)d_in[4];
  const float* W_q  = (const float*)d_in[5];
  const float* b_q  = (const float*)d_in[6];
  const float* W_d  = (const float*)d_in[7];
  const float* b_d  = (const float*)d_in[8];
  float* out = (float*)d_out;

  const int T = in_sizes[0] / (NN * DD);   // 365

  cudaFuncSetAttribute(rgcn_kernel, cudaFuncAttributeMaxDynamicSharedMemorySize,
                       (int)sizeof(Smem));
  rgcn_kernel<<<NCTA, NTH, sizeof(Smem)>>>(x, A, W_ih, W_hh, bias,
                                           W_q, b_q, W_d, b_d, out, T);
}

// round 10
// speedup vs baseline: 3.1213x; 1.2971x over previous
#include <cuda_runtime.h>
#include <cuda_bf16.h>
#include <cstdint>

#define NN   2048
#define DD   16
#define HH   64
#define G4   256
#define NCTA 128
#define ROWS 16
#define NTH  512
#define TKN  256          // nodes (k) per staged tile
#define NKT  (NN / TKN)   // 8 tiles
#define PRT  128          // pair-rows per tile
#define QP   72           // padded pair-row (u32 units) -> conflict-free B frags

typedef unsigned long long u64;
typedef unsigned int u32;

// Global scratch (no cudaMalloc)
__device__ u32 g_qb[2][NN / 2][HH];               // q bf16, node-pair packed, dbl buffered
__device__ uint4 g_Afb[(size_t)NCTA * 4096];      // A bf16 mma-fragment order (8MB)
__device__ int g_bar = 0;                         // grid barrier (self-resetting)

struct Smem {
  // qtb: staging buffers; aliased as qred[4][16][64]f32, red[16][16][64]f32, gate_s[16][256]f32
  u32 qtb[2][PRT * QP];     // 73.7 KB
  float W_ih[DD][G4];       // 16 KB
  float W_hh[HH][G4];       // 64 KB
  float W_q [HH][HH];       // 16 KB
  float bias[G4];
  float b_q [HH];
  float W_d [HH];
  float hdup[HH][18][2];    // h duplicated {h,h}, transposed (9.2KB)
  float xdup[DD][18][2];    // x_t duplicated, transposed
};

__device__ __forceinline__ u32 smem_u32(const void* p) { return (u32)__cvta_generic_to_shared(p); }
__device__ __forceinline__ void cp16(u32 dst, const void* src) {
  asm volatile("cp.async.cg.shared.global [%0], [%1], 16;"
               :: "r"(dst), "l"(__cvta_generic_to_global(src)) : "memory");
}
__device__ __forceinline__ u32 bfpack(float lo, float hi) {   // {hi<<16 | lo}
  u32 r; asm("cvt.rn.bf16x2.f32 %0, %1, %2;" : "=r"(r) : "f"(hi), "f"(lo)); return r;
}
__device__ __forceinline__ void mma16(float* c, uint4 a, u32 b0, u32 b1) {
  asm volatile("mma.sync.aligned.m16n8k16.row.col.f32.bf16.bf16.f32 "
               "{%0,%1,%2,%3}, {%4,%5,%6,%7}, {%8,%9}, {%0,%1,%2,%3};"
               : "+f"(c[0]), "+f"(c[1]), "+f"(c[2]), "+f"(c[3])
               : "r"(a.x), "r"(a.y), "r"(a.z), "r"(a.w), "r"(b0), "r"(b1));
}
__device__ __forceinline__ void fma2(u64& d, u64 a, u64 b) {
  asm("fma.rn.f32x2 %0, %1, %2, %0;" : "+l"(d) : "l"(a), "l"(b));
}
__device__ __forceinline__ u64 pack2(float v) {
  u64 r; asm("mov.b64 %0, {%1, %1};" : "=l"(r) : "f"(v)); return r;
}
__device__ __forceinline__ float sigm_f(float x) { return 1.0f / (1.0f + __expf(-x)); }
__device__ __forceinline__ float tanh_f(float x) { return 1.0f - 2.0f / (__expf(2.0f * x) + 1.0f); }

// Stage tile c (256 nodes = 128 pair-rows x 64 cols u32) into qtb[buf]
__device__ __forceinline__ void stage_q(Smem& s, int buf, int c, int p, int tid) {
  #pragma unroll
  for (int i = 0; i < 4; ++i) {
    const int idx = tid + i * NTH;        // 2048 x 16B ops
    const int pr = idx >> 4;
    const int j4 = (idx & 15) << 2;
    cp16(smem_u32(&s.qtb[buf][pr * QP + j4]), &g_qb[p][c * PRT + pr][j4]);
  }
}

__global__ void __launch_bounds__(NTH, 1)
rgcn_kernel(const float* __restrict__ x,    const float* __restrict__ A,
            const float* __restrict__ W_ih, const float* __restrict__ W_hh,
            const float* __restrict__ bias, const float* __restrict__ W_q,
            const float* __restrict__ b_q,  const float* __restrict__ W_d,
            const float* __restrict__ b_d,  float* __restrict__ out, int T)
{
  extern __shared__ unsigned char smem_raw[];
  Smem& s = *reinterpret_cast<Smem*>(smem_raw);

  const int tid = threadIdx.x, wid = tid >> 5, lane = tid & 31;
  const int n_base = blockIdx.x * ROWS;
  const int n   = n_base + wid;             // this warp's node row
  const int j0  = 2 * lane;
  const int rw4 = (wid >> 2) * 4;           // gates/q: 4-row group base
  const int cw  = wid & 3;                  // gates: 64-col block | q: k-slice
  const int gc0 = cw * 64 + j0;

  // ---- weights into shared ----
  for (int i = tid; i < DD * G4; i += NTH) (&s.W_ih[0][0])[i] = W_ih[i];
  for (int i = tid; i < HH * G4; i += NTH) (&s.W_hh[0][0])[i] = W_hh[i];
  for (int i = tid; i < HH * HH; i += NTH) (&s.W_q[0][0])[i]  = W_q[i];
  for (int i = tid; i < G4;      i += NTH) s.bias[i] = bias[i];
  for (int i = tid; i < HH;      i += NTH) { s.b_q[i] = b_q[i]; s.W_d[i] = W_d[i]; }
  for (int i = tid; i < HH * 18 * 2; i += NTH) (&s.hdup[0][0][0])[i] = 0.0f;

  // ---- one-time: pack this CTA's A rows into bf16 mma-fragment order ----
  // read index: tile*512 + wid*32 + lane  (uint4 per warp-lane per tile)
  for (int i = tid; i < 4096; i += NTH) {
    const int tile = i >> 9, w = (i >> 5) & 15, ln = i & 31;
    const int k0 = tile * TKN + (w << 4) + ((ln & 3) << 1);
    const int r = ln >> 2;
    const float* r0 = A + (size_t)(n_base + r) * NN;
    const float* r8 = A + (size_t)(n_base + r + 8) * NN;
    uint4 v;
    v.x = bfpack(__ldg(r0 + k0),     __ldg(r0 + k0 + 1));
    v.y = bfpack(__ldg(r8 + k0),     __ldg(r8 + k0 + 1));
    v.z = bfpack(__ldg(r0 + k0 + 8), __ldg(r0 + k0 + 9));
    v.w = bfpack(__ldg(r8 + k0 + 8), __ldg(r8 + k0 + 9));
    g_Afb[(size_t)blockIdx.x * 4096 + i] = v;
  }
  __syncthreads();
  const float bd = __ldg(b_d);
  const uint4* fragbase = g_Afb + (size_t)blockIdx.x * 4096 + wid * 32 + lane;

  float c0r = 0.0f, c1r = 0.0f;    // cell state in registers

  for (int t = 0; t < T; ++t) {
    const int p = t & 1;

    // ===== stage x_t into duplicated-transposed smem =====
    if (tid < 256) {
      const int r = tid >> 4, d = tid & 15;
      const float xv = __ldg(&x[((size_t)(n_base + r) * T + t) * DD + d]);
      *reinterpret_cast<u64*>(&s.xdup[d][r][0]) = pack2(xv);
    }

    // ===== phase 1: q = tanh(h @ W_q + b_q); warp=(4 rows, k-slice cw*16) =====
    {
      u64 qacc[4] = {0ull, 0ull, 0ull, 0ull};
      #pragma unroll
      for (int kk = 0; kk < 16; ++kk) {
        const int k = (cw << 4) + kk;
        const u64 w2 = *reinterpret_cast<const u64*>(&s.W_q[k][j0]);
        const ulonglong2 h01 = *reinterpret_cast<const ulonglong2*>(&s.hdup[k][rw4][0]);
        const ulonglong2 h23 = *reinterpret_cast<const ulonglong2*>(&s.hdup[k][rw4 + 2][0]);
        fma2(qacc[0], h01.x, w2); fma2(qacc[1], h01.y, w2);
        fma2(qacc[2], h23.x, w2); fma2(qacc[3], h23.y, w2);
      }
      float* qred = reinterpret_cast<float*>(&s.qtb[0][0]);   // [4][16][64]
      #pragma unroll
      for (int rr = 0; rr < 4; ++rr)
        *reinterpret_cast<u64*>(&qred[(cw << 10) + (rw4 + rr) * 64 + j0]) = qacc[rr];
    }
    __syncthreads();
    {
      const float* qred = reinterpret_cast<const float*>(&s.qtb[0][0]);
      float2 qs = make_float2(s.b_q[j0], s.b_q[j0 + 1]);
      #pragma unroll
      for (int kq = 0; kq < 4; ++kq) {
        const float2 v = *reinterpret_cast<const float2*>(&qred[(kq << 10) + wid * 64 + j0]);
        qs.x += v.x; qs.y += v.y;
      }
      // write bf16 halves into node-pair layout: g_qb[p][n>>1][j] halfword (n&1)
      __nv_bfloat16* h0p = reinterpret_cast<__nv_bfloat16*>(&g_qb[p][n >> 1][j0]) + (n & 1);
      __nv_bfloat16* h1p = reinterpret_cast<__nv_bfloat16*>(&g_qb[p][n >> 1][j0 + 1]) + (n & 1);
      *h0p = __float2bfloat16_rn(tanh_f(qs.x));
      *h1p = __float2bfloat16_rn(tanh_f(qs.y));
    }

    // ===== barrier ARRIVE (release q writes) =====
    __threadfence();
    __syncthreads();
    if (tid == 0) atomicAdd(&g_bar, 1);

    // ===== gates: warp=(4 rows rw4.., 64-col block cw); overlaps barrier skew =====
    u64 accg[4];
    {
      const u64 b2 = *reinterpret_cast<const u64*>(&s.bias[gc0]);
      accg[0] = b2; accg[1] = b2; accg[2] = b2; accg[3] = b2;
      #pragma unroll
      for (int d = 0; d < DD; ++d) {
        const u64 w2 = *reinterpret_cast<const u64*>(&s.W_ih[d][gc0]);
        const ulonglong2 x01 = *reinterpret_cast<const ulonglong2*>(&s.xdup[d][rw4][0]);
        const ulonglong2 x23 = *reinterpret_cast<const ulonglong2*>(&s.xdup[d][rw4 + 2][0]);
        fma2(accg[0], x01.x, w2); fma2(accg[1], x01.y, w2);
        fma2(accg[2], x23.x, w2); fma2(accg[3], x23.y, w2);
      }
      #pragma unroll 8
      for (int k = 0; k < HH; ++k) {
        const u64 w2 = *reinterpret_cast<const u64*>(&s.W_hh[k][gc0]);
        const ulonglong2 h01 = *reinterpret_cast<const ulonglong2*>(&s.hdup[k][rw4][0]);
        const ulonglong2 h23 = *reinterpret_cast<const ulonglong2*>(&s.hdup[k][rw4 + 2][0]);
        fma2(accg[0], h01.x, w2); fma2(accg[1], h01.y, w2);
        fma2(accg[2], h23.x, w2); fma2(accg[3], h23.y, w2);
      }
    }

    // ===== barrier WAIT (acquire all q) =====
    if (tid == 0) {
      const int target = NCTA * (t + 1);
      while (*((volatile int*)&g_bar) < target) { }
    }
    __syncthreads();

    // ===== phase 2: D[16x64] = A_rows @ q via bf16 mma, k-split 16 warps =====
    float acc[32];
    #pragma unroll
    for (int i = 0; i < 32; ++i) acc[i] = 0.0f;

    stage_q(s, 0, 0, p, tid);
    asm volatile("cp.async.commit_group;" ::: "memory");
    uint4 frag = *fragbase;

    const int prA  = (wid << 3) + (lane & 3);   // warp's pair-row base in tile
    const int bcol = lane >> 2;

    #pragma unroll 1
    for (int c = 0; c < NKT; ++c) {
      if (c + 1 < NKT) {
        stage_q(s, (c + 1) & 1, c + 1, p, tid);
        asm volatile("cp.async.commit_group;" ::: "memory");
        asm volatile("cp.async.wait_group 1;" ::: "memory");
      } else {
        asm volatile("cp.async.wait_group 0;" ::: "memory");
      }
      __syncthreads();

      uint4 nfrag;
      if (c + 1 < NKT) nfrag = fragbase[(c + 1) * 512];

      const u32* brow = &s.qtb[c & 1][prA * QP + bcol];
      #pragma unroll
      for (int nc = 0; nc < 8; ++nc) {
        const u32 b0 = brow[nc * 8];
        const u32 b1 = brow[4 * QP + nc * 8];
        mma16(acc + nc * 4, frag, b0, b1);
      }
      frag = nfrag;
      __syncthreads();
    }

    // ===== reduce A@q k-split partials (red[16][16][64] aliases qtb) =====
    float* red = reinterpret_cast<float*>(&s.qtb[0][0]);
    {
      const int r = lane >> 2, cc = (lane & 3) * 2;
      #pragma unroll
      for (int nc = 0; nc < 8; ++nc) {
        *reinterpret_cast<float2*>(&red[wid * 1024 + r * 64 + nc * 8 + cc]) =
            make_float2(acc[nc * 4 + 0], acc[nc * 4 + 1]);
        *reinterpret_cast<float2*>(&red[wid * 1024 + (r + 8) * 64 + nc * 8 + cc]) =
            make_float2(acc[nc * 4 + 2], acc[nc * 4 + 3]);
      }
    }
    __syncthreads();
    float2 aqv = make_float2(0.0f, 0.0f);
    #pragma unroll
    for (int w2 = 0; w2 < 16; ++w2) {
      const float2 v = *reinterpret_cast<const float2*>(&red[w2 * 1024 + wid * 64 + j0]);
      aqv.x += v.x; aqv.y += v.y;
    }
    __syncthreads();

    // ===== redistribute gates -> row-major gate_s =====
    float* gs = reinterpret_cast<float*>(&s.qtb[0][0]);   // [16][256]
    #pragma unroll
    for (int rr = 0; rr < 4; ++rr)
      *reinterpret_cast<u64*>(&gs[(rw4 + rr) * 256 + gc0]) = accg[rr];
    __syncthreads();

    // ===== activations + state update (warp wid owns row wid) =====
    {
      const float2 gi = *reinterpret_cast<const float2*>(&gs[wid * 256 +   0 + j0]);
      const float2 gf = *reinterpret_cast<const float2*>(&gs[wid * 256 +  64 + j0]);
      const float2 gg = *reinterpret_cast<const float2*>(&gs[wid * 256 + 128 + j0]);
      const float2 go = *reinterpret_cast<const float2*>(&gs[wid * 256 + 192 + j0]);

      const float i0 = sigm_f(gi.x), i1 = sigm_f(gi.y);
      const float f0 = sigm_f(gf.x), f1 = sigm_f(gf.y);
      const float g0 = tanh_f(gg.x), g1 = tanh_f(gg.y);
      const float o0 = sigm_f(go.x), o1 = sigm_f(go.y);

      c0r = f0 * (c0r + aqv.x) + i0 * g0;
      c1r = f1 * (c1r + aqv.y) + i1 * g1;
      const float h0 = o0 * tanh_f(c0r);
      const float h1 = o1 * tanh_f(c1r);

      *reinterpret_cast<u64*>(&s.hdup[j0    ][wid][0]) = pack2(h0);
      *reinterpret_cast<u64*>(&s.hdup[j0 + 1][wid][0]) = pack2(h1);

      float part = h0 * s.W_d[j0] + h1 * s.W_d[j0 + 1];
      #pragma unroll
      for (int off = 16; off > 0; off >>= 1)
        part += __shfl_down_sync(0xffffffffu, part, off);
      if (lane == 0) out[(size_t)n * T + t] = part + bd;
    }
    __syncthreads();
  }

  // ===== self-resetting barrier counter =====
  if (tid == 0) {
    const int ticket = atomicAdd(&g_bar, 1);
    if (ticket == NCTA * (T + 1) - 1) atomicExch(&g_bar, 0);
  }
}

extern "C" void kernel_launch(void* const* d_in, const int* in_sizes, int n_in,
                              void* d_out, int out_size) {
  const float* x    = (const float*)d_in[0];
  const float* A    = (const float*)d_in[1];
  const float* W_ih = (const float*)d_in[2];
  const float* W_hh = (const float*)d_in[3];
  const float* bias = (const float*)d_in[4];
  const float* W_q  = (const float*)d_in[5];
  const float* b_q  = (const float*)d_in[6];
  const float* W_d  = (const float*)d_in[7];
  const float* b_d  = (const float*)d_in[8];
  float* out = (float*)d_out;

  const int T = in_sizes[0] / (NN * DD);   // 365

  cudaFuncSetAttribute(rgcn_kernel, cudaFuncAttributeMaxDynamicSharedMemorySize,
                       (int)sizeof(Smem));
  rgcn_kernel<<<NCTA, NTH, sizeof(Smem)>>>(x, A, W_ih, W_hh, bias,
                                           W_q, b_q, W_d, b_d, out, T);
}